// round 13
// baseline (speedup 1.0000x reference)
#include <cuda_runtime.h>
#include <cuda_bf16.h>
#include <cstdint>

#define Hh 100
#define HP 128
#define Bb 64
#define Ss 384
#define Ll 2
#define EPSV 1e-6f
#define NEG_INF (-3.402823466e38f)

typedef unsigned long long ull;

// ---------------- packed f32x2 helpers ----------------
__device__ __forceinline__ ull pk(float x, float y) {
    ull r; asm("mov.b64 %0, {%1,%2};" : "=l"(r) : "f"(x), "f"(y)); return r;
}
__device__ __forceinline__ void upk(ull v, float& x, float& y) {
    asm("mov.b64 {%0,%1}, %2;" : "=f"(x), "=f"(y) : "l"(v));
}
__device__ __forceinline__ ull fma2(ull a, ull b, ull c) {
    ull d; asm("fma.rn.f32x2 %0, %1, %2, %3;" : "=l"(d) : "l"(a), "l"(b), "l"(c)); return d;
}
__device__ __forceinline__ void cpa16(uint32_t s, const void* g) {
    asm volatile("cp.async.cg.shared.global [%0], [%1], 16;\n" :: "r"(s), "l"(g));
}
#define CPA_COMMIT() asm volatile("cp.async.commit_group;\n" ::: "memory")
#define CPA_WAIT1()  asm volatile("cp.async.wait_group 1;\n" ::: "memory")

// ---------------- scratch ----------------
__device__ float g_pT[2][Bb * Ss * HP];
__device__ float g_qT[2][Bb * Ss * HP];
__device__ float g_qTj[2][Bb * HP * Ss];  // [dir][(b*HP+h)*Ss + j]
__device__ float g_att[2][Bb * Ss * Ss];  // per-direction

__device__ float g_inv_np [2][Bb * Ss];
__device__ float g_inv_nq [2][Bb * Ss];
__device__ float g_inv_w1p[2][2][Bb * Ss];
__device__ float g_inv_w2p[2][2][Bb * Ss];
__device__ float g_inv_w3p[2][2][Bb * Ss];
__device__ float g_inv_w4p[2][2][Bb * Ss];
__device__ float g_inv_w2q[2][2][Bb * Ss];
__device__ float g_inv_w4q[2][2][Bb * Ss];
__device__ float g_inv_w1ql[2][2][Bb];
__device__ float g_rowinv[2][Bb * Ss];
__device__ int   g_idx   [2][Bb * Ss];

__device__ __forceinline__ float invclamp(float s) {
    return 1.0f / fmaxf(sqrtf(s), EPSV);
}
__device__ __forceinline__ float wred(float v) {
    #pragma unroll
    for (int off = 16; off >= 1; off >>= 1) v += __shfl_xor_sync(0xffffffffu, v, off);
    return v;
}

// ================ transpose + per-column norms body (uses dyn smem) ================
// smem floats: sm[100*65] @0, wsq[8*100] @6500  (total 7300 floats = 29.2KB)
#define TR_SMEM_FLOATS 7300
#define TR_SMEM_BYTES (TR_SMEM_FLOATS * 4)

__device__ __forceinline__ void transpose_body(
    const int dir, const int kind, float* smf,
    const float* __restrict__ p_f, const float* __restrict__ p_b,
    const float* __restrict__ q_f, const float* __restrict__ q_b,
    const float* __restrict__ w1f, const float* __restrict__ w1b,
    const float* __restrict__ w2f, const float* __restrict__ w2b,
    const float* __restrict__ w3f, const float* __restrict__ w4f)
{
    float* sm  = smf;          // [h][i] stride 65
    float* wsq = smf + 6500;   // [k][h] stride 100

    const float* src = (kind == 0) ? (dir ? p_b : p_f) : (dir ? q_b : q_f);
    float* dst = (kind == 0) ? g_pT[dir] : g_qT[dir];
    const int b = blockIdx.y;
    const int i0 = blockIdx.x * 64;
    const int tid = threadIdx.x;

    {
        const float* wptr[4] = {dir ? w1b : w1f, dir ? w2b : w2f, w3f, w4f};
        for (int e = tid; e < 800; e += 256) {
            int kid = e / 200, rem = e % 200, l = rem / 100, h = rem % 100;
            float w = wptr[kid][l * Hh + h];
            wsq[(kid * 2 + l) * 100 + h] = w * w;
        }
    }
    for (int e = tid; e < Hh * 64; e += 256) {
        int h = e / 64, i = e % 64;
        sm[h * 65 + i] = src[(h * Bb + b) * Ss + i0 + i];
    }
    __syncthreads();

    for (int e = tid; e < 64 * (HP / 4); e += 256) {
        int i = e / (HP / 4), h4 = (e % (HP / 4)) * 4;
        float4 v;
        v.x = (h4 + 0 < Hh) ? sm[(h4 + 0) * 65 + i] : 0.0f;
        v.y = (h4 + 1 < Hh) ? sm[(h4 + 1) * 65 + i] : 0.0f;
        v.z = (h4 + 2 < Hh) ? sm[(h4 + 2) * 65 + i] : 0.0f;
        v.w = (h4 + 3 < Hh) ? sm[(h4 + 3) * 65 + i] : 0.0f;
        *(float4*)&dst[(b * Ss + i0 + i) * HP + h4] = v;
    }
    if (kind == 1) {
        float* dst2 = g_qTj[dir];
        for (int e = tid; e < Hh * 64; e += 256) {
            int h = e / 64, i = e % 64;
            dst2[(b * HP + h) * Ss + i0 + i] = sm[h * 65 + i];
        }
    }

    // fused norms: 4 threads per column
    {
        const int c = tid >> 2, pp = tid & 3;
        float s[9];
        #pragma unroll
        for (int k = 0; k < 9; ++k) s[k] = 0.f;
        for (int h = pp; h < Hh; h += 4) {
            float v = sm[h * 65 + c], v2 = v * v;
            s[0] += v2;
            #pragma unroll
            for (int k = 0; k < 8; ++k) s[1 + k] += wsq[k * 100 + h] * v2;
        }
        #pragma unroll
        for (int off = 2; off >= 1; off >>= 1)
            #pragma unroll
            for (int k = 0; k < 9; ++k) s[k] += __shfl_xor_sync(0xffffffffu, s[k], off, 4);
        if (pp == 0) {
            int ci = b * Ss + i0 + c;
            if (kind == 0) {
                g_inv_np[dir][ci] = invclamp(s[0]);
                #pragma unroll
                for (int l = 0; l < 2; ++l) {
                    g_inv_w1p[dir][l][ci] = invclamp(s[1 + 0 + l]);
                    g_inv_w2p[dir][l][ci] = invclamp(s[1 + 2 + l]);
                    g_inv_w3p[dir][l][ci] = invclamp(s[1 + 4 + l]);
                    g_inv_w4p[dir][l][ci] = invclamp(s[1 + 6 + l]);
                }
            } else {
                g_inv_nq[dir][ci] = invclamp(s[0]);
                #pragma unroll
                for (int l = 0; l < 2; ++l) {
                    g_inv_w2q[dir][l][ci] = invclamp(s[1 + 2 + l]);
                    g_inv_w4q[dir][l][ci] = invclamp(s[1 + 6 + l]);
                }
                if (i0 + c == Ss - 1) {
                    #pragma unroll
                    for (int l = 0; l < 2; ++l)
                        g_inv_w1ql[dir][l][b] = invclamp(s[1 + 0 + l]);
                }
            }
        }
    }
}

// ================= cross body (one direction, one 64-row i tile) =================
// dyn smem (floats): As0[100*68] @0, Asa @6800, Asb @13600, Braw[2][50*64] @20400/@23600
#define CROSS_SMEM_FLOATS 26800
#define CROSS_SMEM_BYTES (CROSS_SMEM_FLOATS * 4)

__device__ __forceinline__ void cross_body(
    const int d, const int b, const int i0, float* smf,
    const float* __restrict__ w2f, const float* __restrict__ w2b,
    float* __restrict__ out)
{
    float* As0 = smf;
    float* Asa = smf + 6800;
    float* Asb = smf + 13600;

    const int tid = threadIdx.x, tx = tid & 15, ty = tid >> 4;
    const uint32_t smem_u32 = (uint32_t)__cvta_generic_to_shared(smf);
    float* attd = g_att[d];
    const float* wa2 = d ? w2b : w2f;

    // A prep: 3 scaled variants [h][i]; w2^2 inline
    {
        const float* srcA = &g_pT[d][(b * Ss + i0) * HP];
        for (int e = tid; e < 64 * 25; e += 256) {
            int i = e / 25, hc = e % 25;
            float4 v = *(const float4*)&srcA[i * HP + hc * 4];
            float vv[4] = {v.x, v.y, v.z, v.w};
            #pragma unroll
            for (int k = 0; k < 4; ++k) {
                int h = hc * 4 + k;
                float wA = __ldg(&wa2[h]);
                float wB = __ldg(&wa2[Hh + h]);
                float w0 = wA * wA, w1 = wB * wB;
                As0[h * 68 + i] = vv[k];
                Asa[h * 68 + i] = vv[k] * w0;
                Asb[h * 68 + i] = vv[k] * w1;
            }
        }
    }

    float inp[4], iw0[4], iw1[4];
    #pragma unroll
    for (int ii = 0; ii < 4; ++ii) {
        int ci = b * Ss + i0 + ty * 4 + ii;
        inp[ii] = g_inv_np[d][ci];
        iw0[ii] = g_inv_w2p[d][0][ci];
        iw1[ii] = g_inv_w2p[d][1][ci];
    }
    float rsum[4] = {0.f, 0.f, 0.f, 0.f};
    float rmax[4] = {NEG_INF, NEG_INF, NEG_INF, NEG_INF};
    int   rarg[4] = {0, 0, 0, 0};
    float m2m[2][4] = {{NEG_INF, NEG_INF, NEG_INF, NEG_INF}, {NEG_INF, NEG_INF, NEG_INF, NEG_INF}};

    ull acc[3][2][4];

    auto prefetch = [&](int kk) {
        if (kk < 12) {
            int j0 = (kk >> 1) * 64, hb = (kk & 1) * 50;
            const float* src = &g_qTj[d][(b * HP + hb) * Ss + j0];
            uint32_t dstb = smem_u32 + (20400 + (kk & 1) * 3200) * 4;
            #pragma unroll
            for (int r = 0; r < 4; ++r) {
                int e = tid + r * 256;
                if (e < 800) {
                    int h = e >> 4, jq = (e & 15) * 4;
                    cpa16(dstb + (h * 64 + jq) * 4, src + h * Ss + jq);
                }
            }
        }
        CPA_COMMIT();
    };

    prefetch(0);
    __syncthreads();   // A prep visible before compute
    prefetch(1);

    for (int kk = 0; kk < 12; ++kk) {
        CPA_WAIT1();
        __syncthreads();
        if ((kk & 1) == 0) {
            #pragma unroll
            for (int v = 0; v < 3; ++v)
                #pragma unroll
                for (int ih = 0; ih < 2; ++ih)
                    #pragma unroll
                    for (int jj = 0; jj < 4; ++jj) acc[v][ih][jj] = 0ull;
        }
        {
            const float* Br = smf + 20400 + (kk & 1) * 3200;
            const int hb = (kk & 1) * 50;
            #pragma unroll 5
            for (int h = 0; h < 50; ++h) {
                int hg = hb + h;
                float4 bq = *(const float4*)&Br[h * 64 + tx * 4];
                ull b0 = pk(bq.x, bq.x), b1 = pk(bq.y, bq.y);
                ull b2 = pk(bq.z, bq.z), b3 = pk(bq.w, bq.w);
                ulonglong2 a0 = *(const ulonglong2*)&As0[hg * 68 + ty * 4];
                ulonglong2 aa = *(const ulonglong2*)&Asa[hg * 68 + ty * 4];
                ulonglong2 ab = *(const ulonglong2*)&Asb[hg * 68 + ty * 4];
                acc[0][0][0] = fma2(a0.x, b0, acc[0][0][0]);
                acc[0][1][0] = fma2(a0.y, b0, acc[0][1][0]);
                acc[1][0][0] = fma2(aa.x, b0, acc[1][0][0]);
                acc[1][1][0] = fma2(aa.y, b0, acc[1][1][0]);
                acc[2][0][0] = fma2(ab.x, b0, acc[2][0][0]);
                acc[2][1][0] = fma2(ab.y, b0, acc[2][1][0]);
                acc[0][0][1] = fma2(a0.x, b1, acc[0][0][1]);
                acc[0][1][1] = fma2(a0.y, b1, acc[0][1][1]);
                acc[1][0][1] = fma2(aa.x, b1, acc[1][0][1]);
                acc[1][1][1] = fma2(aa.y, b1, acc[1][1][1]);
                acc[2][0][1] = fma2(ab.x, b1, acc[2][0][1]);
                acc[2][1][1] = fma2(ab.y, b1, acc[2][1][1]);
                acc[0][0][2] = fma2(a0.x, b2, acc[0][0][2]);
                acc[0][1][2] = fma2(a0.y, b2, acc[0][1][2]);
                acc[1][0][2] = fma2(aa.x, b2, acc[1][0][2]);
                acc[1][1][2] = fma2(aa.y, b2, acc[1][1][2]);
                acc[2][0][2] = fma2(ab.x, b2, acc[2][0][2]);
                acc[2][1][2] = fma2(ab.y, b2, acc[2][1][2]);
                acc[0][0][3] = fma2(a0.x, b3, acc[0][0][3]);
                acc[0][1][3] = fma2(a0.y, b3, acc[0][1][3]);
                acc[1][0][3] = fma2(aa.x, b3, acc[1][0][3]);
                acc[1][1][3] = fma2(aa.y, b3, acc[1][1][3]);
                acc[2][0][3] = fma2(ab.x, b3, acc[2][0][3]);
                acc[2][1][3] = fma2(ab.y, b3, acc[2][1][3]);
            }
        }
        if (kk & 1) {
            const int j0 = (kk >> 1) * 64;
            float inq[4], iq0v[4], iq1v[4];
            #pragma unroll
            for (int jj = 0; jj < 4; ++jj) {
                int cj = b * Ss + j0 + tx * 4 + jj;
                inq[jj]  = g_inv_nq[d][cj];
                iq0v[jj] = g_inv_w2q[d][0][cj];
                iq1v[jj] = g_inv_w2q[d][1][cj];
            }
            float attv[4][4];
            #pragma unroll
            for (int ih = 0; ih < 2; ++ih) {
                #pragma unroll
                for (int jj = 0; jj < 4; ++jj) {
                    float x, y;
                    upk(acc[0][ih][jj], x, y);
                    attv[ih * 2 + 0][jj] = x * inp[ih * 2 + 0] * inq[jj];
                    attv[ih * 2 + 1][jj] = y * inp[ih * 2 + 1] * inq[jj];
                    upk(acc[1][ih][jj], x, y);
                    m2m[0][ih * 2 + 0] = fmaxf(m2m[0][ih * 2 + 0], x * iw0[ih * 2 + 0] * iq0v[jj]);
                    m2m[0][ih * 2 + 1] = fmaxf(m2m[0][ih * 2 + 1], y * iw0[ih * 2 + 1] * iq0v[jj]);
                    upk(acc[2][ih][jj], x, y);
                    m2m[1][ih * 2 + 0] = fmaxf(m2m[1][ih * 2 + 0], x * iw1[ih * 2 + 0] * iq1v[jj]);
                    m2m[1][ih * 2 + 1] = fmaxf(m2m[1][ih * 2 + 1], y * iw1[ih * 2 + 1] * iq1v[jj]);
                }
            }
            #pragma unroll
            for (int ii = 0; ii < 4; ++ii) {
                float* attp = &attd[(b * Ss + i0 + ty * 4 + ii) * Ss + j0 + tx * 4];
                *(float4*)attp = make_float4(attv[ii][0], attv[ii][1], attv[ii][2], attv[ii][3]);
                #pragma unroll
                for (int jj = 0; jj < 4; ++jj) {
                    rsum[ii] += attv[ii][jj];
                    if (attv[ii][jj] > rmax[ii]) { rmax[ii] = attv[ii][jj]; rarg[ii] = j0 + tx * 4 + jj; }
                }
            }
        }
        __syncthreads();
        prefetch(kk + 2);
    }

    #pragma unroll
    for (int ii = 0; ii < 4; ++ii) {
        float s = rsum[ii], mx = rmax[ii];
        int ag = rarg[ii];
        float m0 = m2m[0][ii], m1v = m2m[1][ii];
        #pragma unroll
        for (int off = 8; off >= 1; off >>= 1) {
            s += __shfl_xor_sync(0xffffffffu, s, off, 16);
            float omx = __shfl_xor_sync(0xffffffffu, mx, off, 16);
            int   oag = __shfl_xor_sync(0xffffffffu, ag, off, 16);
            if (omx > mx || (omx == mx && oag < ag)) { mx = omx; ag = oag; }
            m0  = fmaxf(m0,  __shfl_xor_sync(0xffffffffu, m0,  off, 16));
            m1v = fmaxf(m1v, __shfl_xor_sync(0xffffffffu, m1v, off, 16));
        }
        if (tx == 0) {
            int i = i0 + ty * 4 + ii;
            int ci = b * Ss + i;
            g_rowinv[d][ci] = 1.0f / s;
            g_idx[d][ci] = ag;
            out[(((2 + d) * Ss + i) * Bb + b) * Ll + 0] = m0;
            out[(((2 + d) * Ss + i) * Bb + b) * Ll + 1] = m1v;
        }
    }
}

// ================= hmean body, 64-i / 256-thr (used inside fused) =================
// dyn smem (floats): att[2][64*36] @0/@2304, q[2][32*128] @4608/@8704, ws3 @12800
__device__ __forceinline__ void hmean_body(
    const int d, const int b, const int i0, float* hsm,
    const float* __restrict__ w3f, float* __restrict__ out)
{
    float* ws3 = hsm + 12800;

    const int tid = threadIdx.x, tx = tid & 15, ty = tid >> 4;
    const uint32_t smem_u32 = (uint32_t)__cvta_generic_to_shared(hsm);
    const float* attd = g_att[d];

    if (tid < HP) {
        float a = (tid < Hh) ? w3f[tid] : 0.0f;
        float c = (tid < Hh) ? w3f[Hh + tid] : 0.0f;
        ws3[tid] = a * a;
        ws3[HP + tid] = c * c;
    }

    ull hm[4][4];
    #pragma unroll
    for (int ii = 0; ii < 4; ++ii)
        #pragma unroll
        for (int k = 0; k < 4; ++k) hm[ii][k] = 0ull;

    const int hq = tx * 2;

    auto prefetch = [&](int s) {
        if (s < 12) {
            int j0 = s * 32, buf = s & 1;
            uint32_t attb = smem_u32 + (buf * 2304) * 4;
            const float* asrc = &attd[(b * Ss + i0) * Ss + j0];
            #pragma unroll
            for (int r = 0; r < 2; ++r) {
                int e = tid + r * 256;
                int i = e >> 3, c = e & 7;
                cpa16(attb + (i * 36 + c * 4) * 4, asrc + i * Ss + c * 4);
            }
            uint32_t qb = smem_u32 + (4608 + buf * 4096) * 4;
            const float* qsrc = &g_qT[d][(b * Ss + j0) * HP];
            #pragma unroll
            for (int r = 0; r < 4; ++r) {
                int e = tid + r * 256;
                cpa16(qb + e * 16, qsrc + e * 4);
            }
        }
        CPA_COMMIT();
    };

    prefetch(0);
    prefetch(1);

    for (int s = 0; s < 12; ++s) {
        CPA_WAIT1();
        __syncthreads();
        {
            const float* atts = hsm + (s & 1) * 2304;
            const float* qs = hsm + 4608 + (s & 1) * 4096;
            #pragma unroll
            for (int j4 = 0; j4 < 32; j4 += 4) {
                float a[4][4];
                #pragma unroll
                for (int ii = 0; ii < 4; ++ii) {
                    float4 av = *(const float4*)&atts[(ty * 4 + ii) * 36 + j4];
                    a[ii][0] = av.x; a[ii][1] = av.y; a[ii][2] = av.z; a[ii][3] = av.w;
                }
                #pragma unroll
                for (int jj = 0; jj < 4; ++jj) {
                    const float* qrow = &qs[(j4 + jj) * HP + hq];
                    ull q0 = *(const ull*)&qrow[0];
                    ull q1 = *(const ull*)&qrow[32];
                    ull q2 = *(const ull*)&qrow[64];
                    ull q3 = *(const ull*)&qrow[96];
                    ull ap;
                    ap = pk(a[0][jj], a[0][jj]);
                    hm[0][0] = fma2(ap, q0, hm[0][0]); hm[0][1] = fma2(ap, q1, hm[0][1]);
                    hm[0][2] = fma2(ap, q2, hm[0][2]); hm[0][3] = fma2(ap, q3, hm[0][3]);
                    ap = pk(a[1][jj], a[1][jj]);
                    hm[1][0] = fma2(ap, q0, hm[1][0]); hm[1][1] = fma2(ap, q1, hm[1][1]);
                    hm[1][2] = fma2(ap, q2, hm[1][2]); hm[1][3] = fma2(ap, q3, hm[1][3]);
                    ap = pk(a[2][jj], a[2][jj]);
                    hm[2][0] = fma2(ap, q0, hm[2][0]); hm[2][1] = fma2(ap, q1, hm[2][1]);
                    hm[2][2] = fma2(ap, q2, hm[2][2]); hm[2][3] = fma2(ap, q3, hm[2][3]);
                    ap = pk(a[3][jj], a[3][jj]);
                    hm[3][0] = fma2(ap, q0, hm[3][0]); hm[3][1] = fma2(ap, q1, hm[3][1]);
                    hm[3][2] = fma2(ap, q2, hm[3][2]); hm[3][3] = fma2(ap, q3, hm[3][3]);
                }
            }
        }
        __syncthreads();
        prefetch(s + 2);
    }

    #pragma unroll
    for (int ii = 0; ii < 4; ++ii) {
        int i = i0 + ty * 4 + ii;
        int ci = b * Ss + i;
        const float* prow = &g_pT[d][ci * HP];
        float s1a = 0.f, s1b = 0.f, s2a = 0.f, s2b = 0.f;
        #pragma unroll
        for (int k = 0; k < 4; ++k) {
            int hh = hq + 32 * k;
            float hx, hy; upk(hm[ii][k], hx, hy);
            float2 pxy = *(const float2*)&prow[hh];
            float2 w0  = *(const float2*)&ws3[hh];
            float2 w1  = *(const float2*)&ws3[HP + hh];
            s1a += w0.x * pxy.x * hx + w0.y * pxy.y * hy;
            s2a += w0.x * hx * hx + w0.y * hy * hy;
            s1b += w1.x * pxy.x * hx + w1.y * pxy.y * hy;
            s2b += w1.x * hx * hx + w1.y * hy * hy;
        }
        #pragma unroll
        for (int off = 8; off >= 1; off >>= 1) {
            s1a += __shfl_xor_sync(0xffffffffu, s1a, off, 16);
            s2a += __shfl_xor_sync(0xffffffffu, s2a, off, 16);
            s1b += __shfl_xor_sync(0xffffffffu, s1b, off, 16);
            s2b += __shfl_xor_sync(0xffffffffu, s2b, off, 16);
        }
        if (tx == 0) {
            float r = g_rowinv[d][ci];
            float ar = fabsf(r);
            float m30 = (r * s1a) * g_inv_w3p[d][0][ci] / fmaxf(ar * sqrtf(s2a), EPSV);
            float m31 = (r * s1b) * g_inv_w3p[d][1][ci] / fmaxf(ar * sqrtf(s2b), EPSV);
            out[(((4 + d) * Ss + i) * Bb + b) * Ll + 0] = m30;
            out[(((4 + d) * Ss + i) * Bb + b) * Ll + 1] = m31;
        }
    }
}

// ================= hmean body, 32-i / 128-thr (trailing launch) =================
// dyn smem (floats): att[2][32*36] @0/@1152, q[2][32*128] @2304/@6400, ws3 @10496
#define HM32_SMEM_FLOATS 10752
#define HM32_SMEM_BYTES (HM32_SMEM_FLOATS * 4)

__device__ __forceinline__ void hmean32_body(
    const int d, const int b, const int i0, float* hsm,
    const float* __restrict__ w3f, float* __restrict__ out)
{
    float* ws3 = hsm + 10496;

    const int tid = threadIdx.x, tx = tid & 15, ty = tid >> 4;   // ty 0..7
    const uint32_t smem_u32 = (uint32_t)__cvta_generic_to_shared(hsm);
    const float* attd = g_att[d];

    {
        float a = (tid < Hh) ? w3f[tid] : 0.0f;
        float c = (tid < Hh) ? w3f[Hh + tid] : 0.0f;
        ws3[tid] = a * a;
        ws3[HP + tid] = c * c;
    }

    ull hm[4][4];
    #pragma unroll
    for (int ii = 0; ii < 4; ++ii)
        #pragma unroll
        for (int k = 0; k < 4; ++k) hm[ii][k] = 0ull;

    const int hq = tx * 2;

    auto prefetch = [&](int s) {
        if (s < 12) {
            int j0 = s * 32, buf = s & 1;
            uint32_t attb = smem_u32 + (buf * 1152) * 4;
            const float* asrc = &attd[(b * Ss + i0) * Ss + j0];
            #pragma unroll
            for (int r = 0; r < 2; ++r) {
                int e = tid + r * 128;
                int i = e >> 3, c = e & 7;
                cpa16(attb + (i * 36 + c * 4) * 4, asrc + i * Ss + c * 4);
            }
            uint32_t qb = smem_u32 + (2304 + buf * 4096) * 4;
            const float* qsrc = &g_qT[d][(b * Ss + j0) * HP];
            #pragma unroll
            for (int r = 0; r < 8; ++r) {
                int e = tid + r * 128;
                cpa16(qb + e * 16, qsrc + e * 4);
            }
        }
        CPA_COMMIT();
    };

    prefetch(0);
    prefetch(1);

    for (int s = 0; s < 12; ++s) {
        CPA_WAIT1();
        __syncthreads();
        {
            const float* atts = hsm + (s & 1) * 1152;
            const float* qs = hsm + 2304 + (s & 1) * 4096;
            #pragma unroll
            for (int j4 = 0; j4 < 32; j4 += 4) {
                float a[4][4];
                #pragma unroll
                for (int ii = 0; ii < 4; ++ii) {
                    float4 av = *(const float4*)&atts[(ty * 4 + ii) * 36 + j4];
                    a[ii][0] = av.x; a[ii][1] = av.y; a[ii][2] = av.z; a[ii][3] = av.w;
                }
                #pragma unroll
                for (int jj = 0; jj < 4; ++jj) {
                    const float* qrow = &qs[(j4 + jj) * HP + hq];
                    ull q0 = *(const ull*)&qrow[0];
                    ull q1 = *(const ull*)&qrow[32];
                    ull q2 = *(const ull*)&qrow[64];
                    ull q3 = *(const ull*)&qrow[96];
                    ull ap;
                    ap = pk(a[0][jj], a[0][jj]);
                    hm[0][0] = fma2(ap, q0, hm[0][0]); hm[0][1] = fma2(ap, q1, hm[0][1]);
                    hm[0][2] = fma2(ap, q2, hm[0][2]); hm[0][3] = fma2(ap, q3, hm[0][3]);
                    ap = pk(a[1][jj], a[1][jj]);
                    hm[1][0] = fma2(ap, q0, hm[1][0]); hm[1][1] = fma2(ap, q1, hm[1][1]);
                    hm[1][2] = fma2(ap, q2, hm[1][2]); hm[1][3] = fma2(ap, q3, hm[1][3]);
                    ap = pk(a[2][jj], a[2][jj]);
                    hm[2][0] = fma2(ap, q0, hm[2][0]); hm[2][1] = fma2(ap, q1, hm[2][1]);
                    hm[2][2] = fma2(ap, q2, hm[2][2]); hm[2][3] = fma2(ap, q3, hm[2][3]);
                    ap = pk(a[3][jj], a[3][jj]);
                    hm[3][0] = fma2(ap, q0, hm[3][0]); hm[3][1] = fma2(ap, q1, hm[3][1]);
                    hm[3][2] = fma2(ap, q2, hm[3][2]); hm[3][3] = fma2(ap, q3, hm[3][3]);
                }
            }
        }
        __syncthreads();
        prefetch(s + 2);
    }

    #pragma unroll
    for (int ii = 0; ii < 4; ++ii) {
        int i = i0 + ty * 4 + ii;
        int ci = b * Ss + i;
        const float* prow = &g_pT[d][ci * HP];
        float s1a = 0.f, s1b = 0.f, s2a = 0.f, s2b = 0.f;
        #pragma unroll
        for (int k = 0; k < 4; ++k) {
            int hh = hq + 32 * k;
            float hx, hy; upk(hm[ii][k], hx, hy);
            float2 pxy = *(const float2*)&prow[hh];
            float2 w0  = *(const float2*)&ws3[hh];
            float2 w1  = *(const float2*)&ws3[HP + hh];
            s1a += w0.x * pxy.x * hx + w0.y * pxy.y * hy;
            s2a += w0.x * hx * hx + w0.y * hy * hy;
            s1b += w1.x * pxy.x * hx + w1.y * pxy.y * hy;
            s2b += w1.x * hx * hx + w1.y * hy * hy;
        }
        #pragma unroll
        for (int off = 8; off >= 1; off >>= 1) {
            s1a += __shfl_xor_sync(0xffffffffu, s1a, off, 16);
            s2a += __shfl_xor_sync(0xffffffffu, s2a, off, 16);
            s1b += __shfl_xor_sync(0xffffffffu, s1b, off, 16);
            s2b += __shfl_xor_sync(0xffffffffu, s2b, off, 16);
        }
        if (tx == 0) {
            float r = g_rowinv[d][ci];
            float ar = fabsf(r);
            float m30 = (r * s1a) * g_inv_w3p[d][0][ci] / fmaxf(ar * sqrtf(s2a), EPSV);
            float m31 = (r * s1b) * g_inv_w3p[d][1][ci] / fmaxf(ar * sqrtf(s2b), EPSV);
            out[(((4 + d) * Ss + i) * Bb + b) * Ll + 0] = m30;
            out[(((4 + d) * Ss + i) * Bb + b) * Ll + 1] = m31;
        }
    }
}

// ================= m1 + m4 body (128 thr: 4 warps × 16 columns each) =============
__device__ __forceinline__ void m14_body(
    const float* __restrict__ w1f, const float* __restrict__ w1b,
    const float* __restrict__ w4f, float* __restrict__ out)
{
    const int wid = threadIdx.x >> 5, lane = threadIdx.x & 31;
    const int blk = blockIdx.y * 12 + blockIdx.x;          // 0..767

    for (int kc = 0; kc < 16; ++kc) {
        int c2 = (blk * 4 + wid) * 16 + kc;                // 0..49151
        int d = (c2 >= Bb * Ss) ? 1 : 0;
        int c = c2 - d * Bb * Ss;
        int b = c / Ss, i = c % Ss;
        int jm = g_idx[d][c];

        const float* prow = g_pT[d] + c * HP;
        const float* ql = g_qT[d] + (b * Ss + Ss - 1) * HP;
        const float* qm = g_qT[d] + (b * Ss + jm) * HP;
        const float* wa1 = d ? w1b : w1f;

        float s1[2] = {0.f, 0.f}, s4[2] = {0.f, 0.f};
        for (int h = lane; h < Hh; h += 32) {
            float p = prow[h];
            float t1 = p * ql[h];
            float t4 = p * qm[h];
            #pragma unroll
            for (int l = 0; l < 2; ++l) {
                float a;
                a = wa1[l * Hh + h]; s1[l] += a * a * t1;
                a = w4f[l * Hh + h]; s4[l] += a * a * t4;
            }
        }
        #pragma unroll
        for (int l = 0; l < 2; ++l) { s1[l] = wred(s1[l]); s4[l] = wred(s4[l]); }
        if (lane == 0) {
            #pragma unroll
            for (int l = 0; l < 2; ++l) {
                out[(((0 + d) * Ss + i) * Bb + b) * Ll + l] =
                    s1[l] * g_inv_w1p[d][l][c] * g_inv_w1ql[d][l][b];
                out[(((6 + d) * Ss + i) * Bb + b) * Ll + l] =
                    s4[l] * g_inv_w4p[d][l][c] * g_inv_w4q[d][l][b * Ss + jm];
            }
        }
    }
}

// ---------------- kernel wrappers ----------------
// L1: transpose d0 only (z: 0=p, 1=q)
__global__ __launch_bounds__(256) void k_transpose_d0(
    const float* __restrict__ p_f, const float* __restrict__ p_b,
    const float* __restrict__ q_f, const float* __restrict__ q_b,
    const float* __restrict__ w1f, const float* __restrict__ w1b,
    const float* __restrict__ w2f, const float* __restrict__ w2b,
    const float* __restrict__ w3f, const float* __restrict__ w4f)
{
    extern __shared__ float smf[];
    transpose_body(0, blockIdx.z, smf, p_f, p_b, q_f, q_b,
                   w1f, w1b, w2f, w2b, w3f, w4f);
}

// L2: z=0 cross d0; z=1,2 transpose d1 (kind z-1) — d1 transpose rides cross0's tail
__global__ __launch_bounds__(256, 2) void k_phase1(
    const float* __restrict__ p_f, const float* __restrict__ p_b,
    const float* __restrict__ q_f, const float* __restrict__ q_b,
    const float* __restrict__ w1f, const float* __restrict__ w1b,
    const float* __restrict__ w2f, const float* __restrict__ w2b,
    const float* __restrict__ w3f, const float* __restrict__ w4f,
    float* __restrict__ out)
{
    extern __shared__ float smf[];
    if (blockIdx.z == 0)
        cross_body(0, blockIdx.y, blockIdx.x * 64, smf, w2f, w2b, out);
    else
        transpose_body(1, blockIdx.z - 1, smf, p_f, p_b, q_f, q_b,
                       w1f, w1b, w2f, w2b, w3f, w4f);
}

// L3: z=0 cross d1; z=1 hmean d0 (co-resident)
__global__ __launch_bounds__(256, 2) void k_fused(
    const float* __restrict__ w2f, const float* __restrict__ w2b,
    const float* __restrict__ w3f, float* __restrict__ out)
{
    extern __shared__ float smf[];
    if (blockIdx.z == 0)
        cross_body(1, blockIdx.y, blockIdx.x * 64, smf, w2f, w2b, out);
    else
        hmean_body(0, blockIdx.y, blockIdx.x * 64, smf, w3f, out);
}

// L4: z=0 hmean d1 (32-i); z=1 m14 both dirs — m14 fills hmean1's tail
__global__ __launch_bounds__(128) void k_phase3(
    const float* __restrict__ w1f, const float* __restrict__ w1b,
    const float* __restrict__ w3f, const float* __restrict__ w4f,
    float* __restrict__ out)
{
    extern __shared__ float hsm[];
    if (blockIdx.z == 0)
        hmean32_body(1, blockIdx.y, blockIdx.x * 32, hsm, w3f, out);
    else
        m14_body(w1f, w1b, w4f, out);
}

// ---------------- launch ----------------
extern "C" void kernel_launch(void* const* d_in, const int* in_sizes, int n_in,
                              void* d_out, int out_size) {
    const float* p_f = (const float*)d_in[0];
    const float* p_b = (const float*)d_in[1];
    const float* q_f = (const float*)d_in[2];
    const float* q_b = (const float*)d_in[3];
    const float* w1f = (const float*)d_in[4];
    const float* w1b = (const float*)d_in[5];
    const float* w2f = (const float*)d_in[6];
    const float* w2b = (const float*)d_in[7];
    const float* w3f = (const float*)d_in[8];
    // w3b (d_in[9]) intentionally unused: reference uses w3f/w4f for both directions
    const float* w4f = (const float*)d_in[10];
    float* out = (float*)d_out;

    cudaFuncSetAttribute(k_phase1, cudaFuncAttributeMaxDynamicSharedMemorySize,
                         CROSS_SMEM_BYTES);
    cudaFuncSetAttribute(k_fused, cudaFuncAttributeMaxDynamicSharedMemorySize,
                         CROSS_SMEM_BYTES);
    cudaFuncSetAttribute(k_phase3, cudaFuncAttributeMaxDynamicSharedMemorySize,
                         HM32_SMEM_BYTES);

    k_transpose_d0<<<dim3(Ss / 64, Bb, 2), 256, TR_SMEM_BYTES>>>(
        p_f, p_b, q_f, q_b, w1f, w1b, w2f, w2b, w3f, w4f);
    k_phase1<<<dim3(Ss / 64, Bb, 3), 256, CROSS_SMEM_BYTES>>>(
        p_f, p_b, q_f, q_b, w1f, w1b, w2f, w2b, w3f, w4f, out);
    k_fused<<<dim3(Ss / 64, Bb, 2), 256, CROSS_SMEM_BYTES>>>(w2f, w2b, w3f, out);
    k_phase3<<<dim3(Ss / 32, Bb, 2), 128, HM32_SMEM_BYTES>>>(w1f, w1b, w3f, w4f, out);
}

// round 14
// speedup vs baseline: 1.0547x; 1.0547x over previous
#include <cuda_runtime.h>
#include <cuda_bf16.h>
#include <cstdint>

#define Hh 100
#define HP 128
#define Bb 64
#define Ss 384
#define Ll 2
#define EPSV 1e-6f
#define NEG_INF (-3.402823466e38f)

typedef unsigned long long ull;

// ---------------- packed f32x2 helpers ----------------
__device__ __forceinline__ ull pk(float x, float y) {
    ull r; asm("mov.b64 %0, {%1,%2};" : "=l"(r) : "f"(x), "f"(y)); return r;
}
__device__ __forceinline__ void upk(ull v, float& x, float& y) {
    asm("mov.b64 {%0,%1}, %2;" : "=f"(x), "=f"(y) : "l"(v));
}
__device__ __forceinline__ ull fma2(ull a, ull b, ull c) {
    ull d; asm("fma.rn.f32x2 %0, %1, %2, %3;" : "=l"(d) : "l"(a), "l"(b), "l"(c)); return d;
}
__device__ __forceinline__ void cpa16(uint32_t s, const void* g) {
    asm volatile("cp.async.cg.shared.global [%0], [%1], 16;\n" :: "r"(s), "l"(g));
}
#define CPA_COMMIT() asm volatile("cp.async.commit_group;\n" ::: "memory")
#define CPA_WAIT1()  asm volatile("cp.async.wait_group 1;\n" ::: "memory")

// ---------------- scratch ----------------
__device__ float g_pT[2][Bb * Ss * HP];
__device__ float g_qT[2][Bb * Ss * HP];
__device__ float g_qTj[2][Bb * HP * Ss];  // [dir][(b*HP+h)*Ss + j]
__device__ float g_att[2][Bb * Ss * Ss];  // per-direction

__device__ float g_inv_np [2][Bb * Ss];
__device__ float g_inv_nq [2][Bb * Ss];
__device__ float g_inv_w1p[2][2][Bb * Ss];
__device__ float g_inv_w2p[2][2][Bb * Ss];
__device__ float g_inv_w3p[2][2][Bb * Ss];
__device__ float g_inv_w4p[2][2][Bb * Ss];
__device__ float g_inv_w2q[2][2][Bb * Ss];
__device__ float g_inv_w4q[2][2][Bb * Ss];
__device__ float g_inv_w1ql[2][2][Bb];
__device__ float g_rowinv[2][Bb * Ss];
__device__ int   g_idx   [2][Bb * Ss];

__device__ __forceinline__ float invclamp(float s) {
    return 1.0f / fmaxf(sqrtf(s), EPSV);
}
__device__ __forceinline__ float wred(float v) {
    #pragma unroll
    for (int off = 16; off >= 1; off >>= 1) v += __shfl_xor_sync(0xffffffffu, v, off);
    return v;
}

// ================ transpose + per-column norms body (uses dyn smem) ================
// smem floats: sm[100*65] @0, wsq[8*100] @6500  (total 7300 floats = 29.2KB)
#define TR_SMEM_FLOATS 7300
#define TR_SMEM_BYTES (TR_SMEM_FLOATS * 4)

__device__ __forceinline__ void transpose_body(
    const int dir, const int kind, float* smf,
    const float* __restrict__ p_f, const float* __restrict__ p_b,
    const float* __restrict__ q_f, const float* __restrict__ q_b,
    const float* __restrict__ w1f, const float* __restrict__ w1b,
    const float* __restrict__ w2f, const float* __restrict__ w2b,
    const float* __restrict__ w3f, const float* __restrict__ w4f)
{
    float* sm  = smf;          // [h][i] stride 65
    float* wsq = smf + 6500;   // [k][h] stride 100

    const float* src = (kind == 0) ? (dir ? p_b : p_f) : (dir ? q_b : q_f);
    float* dst = (kind == 0) ? g_pT[dir] : g_qT[dir];
    const int b = blockIdx.y;
    const int i0 = blockIdx.x * 64;
    const int tid = threadIdx.x;

    {
        const float* wptr[4] = {dir ? w1b : w1f, dir ? w2b : w2f, w3f, w4f};
        for (int e = tid; e < 800; e += 256) {
            int kid = e / 200, rem = e % 200, l = rem / 100, h = rem % 100;
            float w = wptr[kid][l * Hh + h];
            wsq[(kid * 2 + l) * 100 + h] = w * w;
        }
    }
    for (int e = tid; e < Hh * 64; e += 256) {
        int h = e / 64, i = e % 64;
        sm[h * 65 + i] = src[(h * Bb + b) * Ss + i0 + i];
    }
    __syncthreads();

    for (int e = tid; e < 64 * (HP / 4); e += 256) {
        int i = e / (HP / 4), h4 = (e % (HP / 4)) * 4;
        float4 v;
        v.x = (h4 + 0 < Hh) ? sm[(h4 + 0) * 65 + i] : 0.0f;
        v.y = (h4 + 1 < Hh) ? sm[(h4 + 1) * 65 + i] : 0.0f;
        v.z = (h4 + 2 < Hh) ? sm[(h4 + 2) * 65 + i] : 0.0f;
        v.w = (h4 + 3 < Hh) ? sm[(h4 + 3) * 65 + i] : 0.0f;
        *(float4*)&dst[(b * Ss + i0 + i) * HP + h4] = v;
    }
    if (kind == 1) {
        float* dst2 = g_qTj[dir];
        for (int e = tid; e < Hh * 64; e += 256) {
            int h = e / 64, i = e % 64;
            dst2[(b * HP + h) * Ss + i0 + i] = sm[h * 65 + i];
        }
    }

    // fused norms: 4 threads per column
    {
        const int c = tid >> 2, pp = tid & 3;
        float s[9];
        #pragma unroll
        for (int k = 0; k < 9; ++k) s[k] = 0.f;
        for (int h = pp; h < Hh; h += 4) {
            float v = sm[h * 65 + c], v2 = v * v;
            s[0] += v2;
            #pragma unroll
            for (int k = 0; k < 8; ++k) s[1 + k] += wsq[k * 100 + h] * v2;
        }
        #pragma unroll
        for (int off = 2; off >= 1; off >>= 1)
            #pragma unroll
            for (int k = 0; k < 9; ++k) s[k] += __shfl_xor_sync(0xffffffffu, s[k], off, 4);
        if (pp == 0) {
            int ci = b * Ss + i0 + c;
            if (kind == 0) {
                g_inv_np[dir][ci] = invclamp(s[0]);
                #pragma unroll
                for (int l = 0; l < 2; ++l) {
                    g_inv_w1p[dir][l][ci] = invclamp(s[1 + 0 + l]);
                    g_inv_w2p[dir][l][ci] = invclamp(s[1 + 2 + l]);
                    g_inv_w3p[dir][l][ci] = invclamp(s[1 + 4 + l]);
                    g_inv_w4p[dir][l][ci] = invclamp(s[1 + 6 + l]);
                }
            } else {
                g_inv_nq[dir][ci] = invclamp(s[0]);
                #pragma unroll
                for (int l = 0; l < 2; ++l) {
                    g_inv_w2q[dir][l][ci] = invclamp(s[1 + 2 + l]);
                    g_inv_w4q[dir][l][ci] = invclamp(s[1 + 6 + l]);
                }
                if (i0 + c == Ss - 1) {
                    #pragma unroll
                    for (int l = 0; l < 2; ++l)
                        g_inv_w1ql[dir][l][b] = invclamp(s[1 + 0 + l]);
                }
            }
        }
    }
}

// ================= cross body (one direction, one 64-row i tile) =================
// dyn smem (floats): As0[100*68] @0, Asa @6800, Asb @13600, Braw[2][50*64] @20400/@23600
#define CROSS_SMEM_FLOATS 26800
#define CROSS_SMEM_BYTES (CROSS_SMEM_FLOATS * 4)

__device__ __forceinline__ void cross_body(
    const int d, const int b, const int i0, float* smf,
    const float* __restrict__ w2f, const float* __restrict__ w2b,
    float* __restrict__ out)
{
    float* As0 = smf;
    float* Asa = smf + 6800;
    float* Asb = smf + 13600;

    const int tid = threadIdx.x, tx = tid & 15, ty = tid >> 4;
    const uint32_t smem_u32 = (uint32_t)__cvta_generic_to_shared(smf);
    float* attd = g_att[d];
    const float* wa2 = d ? w2b : w2f;

    // A prep: 3 scaled variants [h][i]; w2^2 inline
    {
        const float* srcA = &g_pT[d][(b * Ss + i0) * HP];
        for (int e = tid; e < 64 * 25; e += 256) {
            int i = e / 25, hc = e % 25;
            float4 v = *(const float4*)&srcA[i * HP + hc * 4];
            float vv[4] = {v.x, v.y, v.z, v.w};
            #pragma unroll
            for (int k = 0; k < 4; ++k) {
                int h = hc * 4 + k;
                float wA = __ldg(&wa2[h]);
                float wB = __ldg(&wa2[Hh + h]);
                float w0 = wA * wA, w1 = wB * wB;
                As0[h * 68 + i] = vv[k];
                Asa[h * 68 + i] = vv[k] * w0;
                Asb[h * 68 + i] = vv[k] * w1;
            }
        }
    }

    float inp[4], iw0[4], iw1[4];
    #pragma unroll
    for (int ii = 0; ii < 4; ++ii) {
        int ci = b * Ss + i0 + ty * 4 + ii;
        inp[ii] = g_inv_np[d][ci];
        iw0[ii] = g_inv_w2p[d][0][ci];
        iw1[ii] = g_inv_w2p[d][1][ci];
    }
    float rsum[4] = {0.f, 0.f, 0.f, 0.f};
    float rmax[4] = {NEG_INF, NEG_INF, NEG_INF, NEG_INF};
    int   rarg[4] = {0, 0, 0, 0};
    float m2m[2][4] = {{NEG_INF, NEG_INF, NEG_INF, NEG_INF}, {NEG_INF, NEG_INF, NEG_INF, NEG_INF}};

    ull acc[3][2][4];

    auto prefetch = [&](int kk) {
        if (kk < 12) {
            int j0 = (kk >> 1) * 64, hb = (kk & 1) * 50;
            const float* src = &g_qTj[d][(b * HP + hb) * Ss + j0];
            uint32_t dstb = smem_u32 + (20400 + (kk & 1) * 3200) * 4;
            #pragma unroll
            for (int r = 0; r < 4; ++r) {
                int e = tid + r * 256;
                if (e < 800) {
                    int h = e >> 4, jq = (e & 15) * 4;
                    cpa16(dstb + (h * 64 + jq) * 4, src + h * Ss + jq);
                }
            }
        }
        CPA_COMMIT();
    };

    prefetch(0);
    __syncthreads();   // A prep visible before compute
    prefetch(1);

    for (int kk = 0; kk < 12; ++kk) {
        CPA_WAIT1();
        __syncthreads();
        if ((kk & 1) == 0) {
            #pragma unroll
            for (int v = 0; v < 3; ++v)
                #pragma unroll
                for (int ih = 0; ih < 2; ++ih)
                    #pragma unroll
                    for (int jj = 0; jj < 4; ++jj) acc[v][ih][jj] = 0ull;
        }
        {
            const float* Br = smf + 20400 + (kk & 1) * 3200;
            const int hb = (kk & 1) * 50;
            #pragma unroll 5
            for (int h = 0; h < 50; ++h) {
                int hg = hb + h;
                float4 bq = *(const float4*)&Br[h * 64 + tx * 4];
                ull b0 = pk(bq.x, bq.x), b1 = pk(bq.y, bq.y);
                ull b2 = pk(bq.z, bq.z), b3 = pk(bq.w, bq.w);
                ulonglong2 a0 = *(const ulonglong2*)&As0[hg * 68 + ty * 4];
                ulonglong2 aa = *(const ulonglong2*)&Asa[hg * 68 + ty * 4];
                ulonglong2 ab = *(const ulonglong2*)&Asb[hg * 68 + ty * 4];
                acc[0][0][0] = fma2(a0.x, b0, acc[0][0][0]);
                acc[0][1][0] = fma2(a0.y, b0, acc[0][1][0]);
                acc[1][0][0] = fma2(aa.x, b0, acc[1][0][0]);
                acc[1][1][0] = fma2(aa.y, b0, acc[1][1][0]);
                acc[2][0][0] = fma2(ab.x, b0, acc[2][0][0]);
                acc[2][1][0] = fma2(ab.y, b0, acc[2][1][0]);
                acc[0][0][1] = fma2(a0.x, b1, acc[0][0][1]);
                acc[0][1][1] = fma2(a0.y, b1, acc[0][1][1]);
                acc[1][0][1] = fma2(aa.x, b1, acc[1][0][1]);
                acc[1][1][1] = fma2(aa.y, b1, acc[1][1][1]);
                acc[2][0][1] = fma2(ab.x, b1, acc[2][0][1]);
                acc[2][1][1] = fma2(ab.y, b1, acc[2][1][1]);
                acc[0][0][2] = fma2(a0.x, b2, acc[0][0][2]);
                acc[0][1][2] = fma2(a0.y, b2, acc[0][1][2]);
                acc[1][0][2] = fma2(aa.x, b2, acc[1][0][2]);
                acc[1][1][2] = fma2(aa.y, b2, acc[1][1][2]);
                acc[2][0][2] = fma2(ab.x, b2, acc[2][0][2]);
                acc[2][1][2] = fma2(ab.y, b2, acc[2][1][2]);
                acc[0][0][3] = fma2(a0.x, b3, acc[0][0][3]);
                acc[0][1][3] = fma2(a0.y, b3, acc[0][1][3]);
                acc[1][0][3] = fma2(aa.x, b3, acc[1][0][3]);
                acc[1][1][3] = fma2(aa.y, b3, acc[1][1][3]);
                acc[2][0][3] = fma2(ab.x, b3, acc[2][0][3]);
                acc[2][1][3] = fma2(ab.y, b3, acc[2][1][3]);
            }
        }
        if (kk & 1) {
            const int j0 = (kk >> 1) * 64;
            float inq[4], iq0v[4], iq1v[4];
            #pragma unroll
            for (int jj = 0; jj < 4; ++jj) {
                int cj = b * Ss + j0 + tx * 4 + jj;
                inq[jj]  = g_inv_nq[d][cj];
                iq0v[jj] = g_inv_w2q[d][0][cj];
                iq1v[jj] = g_inv_w2q[d][1][cj];
            }
            float attv[4][4];
            #pragma unroll
            for (int ih = 0; ih < 2; ++ih) {
                #pragma unroll
                for (int jj = 0; jj < 4; ++jj) {
                    float x, y;
                    upk(acc[0][ih][jj], x, y);
                    attv[ih * 2 + 0][jj] = x * inp[ih * 2 + 0] * inq[jj];
                    attv[ih * 2 + 1][jj] = y * inp[ih * 2 + 1] * inq[jj];
                    upk(acc[1][ih][jj], x, y);
                    m2m[0][ih * 2 + 0] = fmaxf(m2m[0][ih * 2 + 0], x * iw0[ih * 2 + 0] * iq0v[jj]);
                    m2m[0][ih * 2 + 1] = fmaxf(m2m[0][ih * 2 + 1], y * iw0[ih * 2 + 1] * iq0v[jj]);
                    upk(acc[2][ih][jj], x, y);
                    m2m[1][ih * 2 + 0] = fmaxf(m2m[1][ih * 2 + 0], x * iw1[ih * 2 + 0] * iq1v[jj]);
                    m2m[1][ih * 2 + 1] = fmaxf(m2m[1][ih * 2 + 1], y * iw1[ih * 2 + 1] * iq1v[jj]);
                }
            }
            #pragma unroll
            for (int ii = 0; ii < 4; ++ii) {
                float* attp = &attd[(b * Ss + i0 + ty * 4 + ii) * Ss + j0 + tx * 4];
                *(float4*)attp = make_float4(attv[ii][0], attv[ii][1], attv[ii][2], attv[ii][3]);
                #pragma unroll
                for (int jj = 0; jj < 4; ++jj) {
                    rsum[ii] += attv[ii][jj];
                    if (attv[ii][jj] > rmax[ii]) { rmax[ii] = attv[ii][jj]; rarg[ii] = j0 + tx * 4 + jj; }
                }
            }
        }
        __syncthreads();
        prefetch(kk + 2);
    }

    #pragma unroll
    for (int ii = 0; ii < 4; ++ii) {
        float s = rsum[ii], mx = rmax[ii];
        int ag = rarg[ii];
        float m0 = m2m[0][ii], m1v = m2m[1][ii];
        #pragma unroll
        for (int off = 8; off >= 1; off >>= 1) {
            s += __shfl_xor_sync(0xffffffffu, s, off, 16);
            float omx = __shfl_xor_sync(0xffffffffu, mx, off, 16);
            int   oag = __shfl_xor_sync(0xffffffffu, ag, off, 16);
            if (omx > mx || (omx == mx && oag < ag)) { mx = omx; ag = oag; }
            m0  = fmaxf(m0,  __shfl_xor_sync(0xffffffffu, m0,  off, 16));
            m1v = fmaxf(m1v, __shfl_xor_sync(0xffffffffu, m1v, off, 16));
        }
        if (tx == 0) {
            int i = i0 + ty * 4 + ii;
            int ci = b * Ss + i;
            g_rowinv[d][ci] = 1.0f / s;
            g_idx[d][ci] = ag;
            out[(((2 + d) * Ss + i) * Bb + b) * Ll + 0] = m0;
            out[(((2 + d) * Ss + i) * Bb + b) * Ll + 1] = m1v;
        }
    }
}

// ================= hmean body, 64-i / 256-thr (used inside fused) =================
// dyn smem (floats): att[2][64*36] @0/@2304, q[2][32*128] @4608/@8704, ws3 @12800
__device__ __forceinline__ void hmean_body(
    const int d, const int b, const int i0, float* hsm,
    const float* __restrict__ w3f, float* __restrict__ out)
{
    float* ws3 = hsm + 12800;

    const int tid = threadIdx.x, tx = tid & 15, ty = tid >> 4;
    const uint32_t smem_u32 = (uint32_t)__cvta_generic_to_shared(hsm);
    const float* attd = g_att[d];

    if (tid < HP) {
        float a = (tid < Hh) ? w3f[tid] : 0.0f;
        float c = (tid < Hh) ? w3f[Hh + tid] : 0.0f;
        ws3[tid] = a * a;
        ws3[HP + tid] = c * c;
    }

    ull hm[4][4];
    #pragma unroll
    for (int ii = 0; ii < 4; ++ii)
        #pragma unroll
        for (int k = 0; k < 4; ++k) hm[ii][k] = 0ull;

    const int hq = tx * 2;

    auto prefetch = [&](int s) {
        if (s < 12) {
            int j0 = s * 32, buf = s & 1;
            uint32_t attb = smem_u32 + (buf * 2304) * 4;
            const float* asrc = &attd[(b * Ss + i0) * Ss + j0];
            #pragma unroll
            for (int r = 0; r < 2; ++r) {
                int e = tid + r * 256;
                int i = e >> 3, c = e & 7;
                cpa16(attb + (i * 36 + c * 4) * 4, asrc + i * Ss + c * 4);
            }
            uint32_t qb = smem_u32 + (4608 + buf * 4096) * 4;
            const float* qsrc = &g_qT[d][(b * Ss + j0) * HP];
            #pragma unroll
            for (int r = 0; r < 4; ++r) {
                int e = tid + r * 256;
                cpa16(qb + e * 16, qsrc + e * 4);
            }
        }
        CPA_COMMIT();
    };

    prefetch(0);
    prefetch(1);

    for (int s = 0; s < 12; ++s) {
        CPA_WAIT1();
        __syncthreads();
        {
            const float* atts = hsm + (s & 1) * 2304;
            const float* qs = hsm + 4608 + (s & 1) * 4096;
            #pragma unroll
            for (int j4 = 0; j4 < 32; j4 += 4) {
                float a[4][4];
                #pragma unroll
                for (int ii = 0; ii < 4; ++ii) {
                    float4 av = *(const float4*)&atts[(ty * 4 + ii) * 36 + j4];
                    a[ii][0] = av.x; a[ii][1] = av.y; a[ii][2] = av.z; a[ii][3] = av.w;
                }
                #pragma unroll
                for (int jj = 0; jj < 4; ++jj) {
                    const float* qrow = &qs[(j4 + jj) * HP + hq];
                    ull q0 = *(const ull*)&qrow[0];
                    ull q1 = *(const ull*)&qrow[32];
                    ull q2 = *(const ull*)&qrow[64];
                    ull q3 = *(const ull*)&qrow[96];
                    ull ap;
                    ap = pk(a[0][jj], a[0][jj]);
                    hm[0][0] = fma2(ap, q0, hm[0][0]); hm[0][1] = fma2(ap, q1, hm[0][1]);
                    hm[0][2] = fma2(ap, q2, hm[0][2]); hm[0][3] = fma2(ap, q3, hm[0][3]);
                    ap = pk(a[1][jj], a[1][jj]);
                    hm[1][0] = fma2(ap, q0, hm[1][0]); hm[1][1] = fma2(ap, q1, hm[1][1]);
                    hm[1][2] = fma2(ap, q2, hm[1][2]); hm[1][3] = fma2(ap, q3, hm[1][3]);
                    ap = pk(a[2][jj], a[2][jj]);
                    hm[2][0] = fma2(ap, q0, hm[2][0]); hm[2][1] = fma2(ap, q1, hm[2][1]);
                    hm[2][2] = fma2(ap, q2, hm[2][2]); hm[2][3] = fma2(ap, q3, hm[2][3]);
                    ap = pk(a[3][jj], a[3][jj]);
                    hm[3][0] = fma2(ap, q0, hm[3][0]); hm[3][1] = fma2(ap, q1, hm[3][1]);
                    hm[3][2] = fma2(ap, q2, hm[3][2]); hm[3][3] = fma2(ap, q3, hm[3][3]);
                }
            }
        }
        __syncthreads();
        prefetch(s + 2);
    }

    #pragma unroll
    for (int ii = 0; ii < 4; ++ii) {
        int i = i0 + ty * 4 + ii;
        int ci = b * Ss + i;
        const float* prow = &g_pT[d][ci * HP];
        float s1a = 0.f, s1b = 0.f, s2a = 0.f, s2b = 0.f;
        #pragma unroll
        for (int k = 0; k < 4; ++k) {
            int hh = hq + 32 * k;
            float hx, hy; upk(hm[ii][k], hx, hy);
            float2 pxy = *(const float2*)&prow[hh];
            float2 w0  = *(const float2*)&ws3[hh];
            float2 w1  = *(const float2*)&ws3[HP + hh];
            s1a += w0.x * pxy.x * hx + w0.y * pxy.y * hy;
            s2a += w0.x * hx * hx + w0.y * hy * hy;
            s1b += w1.x * pxy.x * hx + w1.y * pxy.y * hy;
            s2b += w1.x * hx * hx + w1.y * hy * hy;
        }
        #pragma unroll
        for (int off = 8; off >= 1; off >>= 1) {
            s1a += __shfl_xor_sync(0xffffffffu, s1a, off, 16);
            s2a += __shfl_xor_sync(0xffffffffu, s2a, off, 16);
            s1b += __shfl_xor_sync(0xffffffffu, s1b, off, 16);
            s2b += __shfl_xor_sync(0xffffffffu, s2b, off, 16);
        }
        if (tx == 0) {
            float r = g_rowinv[d][ci];
            float ar = fabsf(r);
            float m30 = (r * s1a) * g_inv_w3p[d][0][ci] / fmaxf(ar * sqrtf(s2a), EPSV);
            float m31 = (r * s1b) * g_inv_w3p[d][1][ci] / fmaxf(ar * sqrtf(s2b), EPSV);
            out[(((4 + d) * Ss + i) * Bb + b) * Ll + 0] = m30;
            out[(((4 + d) * Ss + i) * Bb + b) * Ll + 1] = m31;
        }
    }
}

// ================= hmean body, 32-i / 128-thr (trailing launch) =================
// dyn smem (floats): att[2][32*36] @0/@1152, q[2][32*128] @2304/@6400, ws3 @10496
#define HM32_SMEM_FLOATS 10752
#define HM32_SMEM_BYTES (HM32_SMEM_FLOATS * 4)

__device__ __forceinline__ void hmean32_body(
    const int d, const int b, const int i0, float* hsm,
    const float* __restrict__ w3f, float* __restrict__ out)
{
    float* ws3 = hsm + 10496;

    const int tid = threadIdx.x, tx = tid & 15, ty = tid >> 4;   // ty 0..7
    const uint32_t smem_u32 = (uint32_t)__cvta_generic_to_shared(hsm);
    const float* attd = g_att[d];

    {
        float a = (tid < Hh) ? w3f[tid] : 0.0f;
        float c = (tid < Hh) ? w3f[Hh + tid] : 0.0f;
        ws3[tid] = a * a;
        ws3[HP + tid] = c * c;
    }

    ull hm[4][4];
    #pragma unroll
    for (int ii = 0; ii < 4; ++ii)
        #pragma unroll
        for (int k = 0; k < 4; ++k) hm[ii][k] = 0ull;

    const int hq = tx * 2;

    auto prefetch = [&](int s) {
        if (s < 12) {
            int j0 = s * 32, buf = s & 1;
            uint32_t attb = smem_u32 + (buf * 1152) * 4;
            const float* asrc = &attd[(b * Ss + i0) * Ss + j0];
            #pragma unroll
            for (int r = 0; r < 2; ++r) {
                int e = tid + r * 128;
                int i = e >> 3, c = e & 7;
                cpa16(attb + (i * 36 + c * 4) * 4, asrc + i * Ss + c * 4);
            }
            uint32_t qb = smem_u32 + (2304 + buf * 4096) * 4;
            const float* qsrc = &g_qT[d][(b * Ss + j0) * HP];
            #pragma unroll
            for (int r = 0; r < 8; ++r) {
                int e = tid + r * 128;
                cpa16(qb + e * 16, qsrc + e * 4);
            }
        }
        CPA_COMMIT();
    };

    prefetch(0);
    prefetch(1);

    for (int s = 0; s < 12; ++s) {
        CPA_WAIT1();
        __syncthreads();
        {
            const float* atts = hsm + (s & 1) * 1152;
            const float* qs = hsm + 2304 + (s & 1) * 4096;
            #pragma unroll
            for (int j4 = 0; j4 < 32; j4 += 4) {
                float a[4][4];
                #pragma unroll
                for (int ii = 0; ii < 4; ++ii) {
                    float4 av = *(const float4*)&atts[(ty * 4 + ii) * 36 + j4];
                    a[ii][0] = av.x; a[ii][1] = av.y; a[ii][2] = av.z; a[ii][3] = av.w;
                }
                #pragma unroll
                for (int jj = 0; jj < 4; ++jj) {
                    const float* qrow = &qs[(j4 + jj) * HP + hq];
                    ull q0 = *(const ull*)&qrow[0];
                    ull q1 = *(const ull*)&qrow[32];
                    ull q2 = *(const ull*)&qrow[64];
                    ull q3 = *(const ull*)&qrow[96];
                    ull ap;
                    ap = pk(a[0][jj], a[0][jj]);
                    hm[0][0] = fma2(ap, q0, hm[0][0]); hm[0][1] = fma2(ap, q1, hm[0][1]);
                    hm[0][2] = fma2(ap, q2, hm[0][2]); hm[0][3] = fma2(ap, q3, hm[0][3]);
                    ap = pk(a[1][jj], a[1][jj]);
                    hm[1][0] = fma2(ap, q0, hm[1][0]); hm[1][1] = fma2(ap, q1, hm[1][1]);
                    hm[1][2] = fma2(ap, q2, hm[1][2]); hm[1][3] = fma2(ap, q3, hm[1][3]);
                    ap = pk(a[2][jj], a[2][jj]);
                    hm[2][0] = fma2(ap, q0, hm[2][0]); hm[2][1] = fma2(ap, q1, hm[2][1]);
                    hm[2][2] = fma2(ap, q2, hm[2][2]); hm[2][3] = fma2(ap, q3, hm[2][3]);
                    ap = pk(a[3][jj], a[3][jj]);
                    hm[3][0] = fma2(ap, q0, hm[3][0]); hm[3][1] = fma2(ap, q1, hm[3][1]);
                    hm[3][2] = fma2(ap, q2, hm[3][2]); hm[3][3] = fma2(ap, q3, hm[3][3]);
                }
            }
        }
        __syncthreads();
        prefetch(s + 2);
    }

    #pragma unroll
    for (int ii = 0; ii < 4; ++ii) {
        int i = i0 + ty * 4 + ii;
        int ci = b * Ss + i;
        const float* prow = &g_pT[d][ci * HP];
        float s1a = 0.f, s1b = 0.f, s2a = 0.f, s2b = 0.f;
        #pragma unroll
        for (int k = 0; k < 4; ++k) {
            int hh = hq + 32 * k;
            float hx, hy; upk(hm[ii][k], hx, hy);
            float2 pxy = *(const float2*)&prow[hh];
            float2 w0  = *(const float2*)&ws3[hh];
            float2 w1  = *(const float2*)&ws3[HP + hh];
            s1a += w0.x * pxy.x * hx + w0.y * pxy.y * hy;
            s2a += w0.x * hx * hx + w0.y * hy * hy;
            s1b += w1.x * pxy.x * hx + w1.y * pxy.y * hy;
            s2b += w1.x * hx * hx + w1.y * hy * hy;
        }
        #pragma unroll
        for (int off = 8; off >= 1; off >>= 1) {
            s1a += __shfl_xor_sync(0xffffffffu, s1a, off, 16);
            s2a += __shfl_xor_sync(0xffffffffu, s2a, off, 16);
            s1b += __shfl_xor_sync(0xffffffffu, s1b, off, 16);
            s2b += __shfl_xor_sync(0xffffffffu, s2b, off, 16);
        }
        if (tx == 0) {
            float r = g_rowinv[d][ci];
            float ar = fabsf(r);
            float m30 = (r * s1a) * g_inv_w3p[d][0][ci] / fmaxf(ar * sqrtf(s2a), EPSV);
            float m31 = (r * s1b) * g_inv_w3p[d][1][ci] / fmaxf(ar * sqrtf(s2b), EPSV);
            out[(((4 + d) * Ss + i) * Bb + b) * Ll + 0] = m30;
            out[(((4 + d) * Ss + i) * Bb + b) * Ll + 1] = m31;
        }
    }
}

// ---------------- kernel wrappers ----------------
// L1: transpose d0 only (z: 0=p, 1=q)
__global__ __launch_bounds__(256) void k_transpose_d0(
    const float* __restrict__ p_f, const float* __restrict__ p_b,
    const float* __restrict__ q_f, const float* __restrict__ q_b,
    const float* __restrict__ w1f, const float* __restrict__ w1b,
    const float* __restrict__ w2f, const float* __restrict__ w2b,
    const float* __restrict__ w3f, const float* __restrict__ w4f)
{
    extern __shared__ float smf[];
    transpose_body(0, blockIdx.z, smf, p_f, p_b, q_f, q_b,
                   w1f, w1b, w2f, w2b, w3f, w4f);
}

// L2: z=0 cross d0; z=1,2 transpose d1 (kind z-1) — d1 transpose rides cross0's tail
__global__ __launch_bounds__(256, 2) void k_phase1(
    const float* __restrict__ p_f, const float* __restrict__ p_b,
    const float* __restrict__ q_f, const float* __restrict__ q_b,
    const float* __restrict__ w1f, const float* __restrict__ w1b,
    const float* __restrict__ w2f, const float* __restrict__ w2b,
    const float* __restrict__ w3f, const float* __restrict__ w4f,
    float* __restrict__ out)
{
    extern __shared__ float smf[];
    if (blockIdx.z == 0)
        cross_body(0, blockIdx.y, blockIdx.x * 64, smf, w2f, w2b, out);
    else
        transpose_body(1, blockIdx.z - 1, smf, p_f, p_b, q_f, q_b,
                       w1f, w1b, w2f, w2b, w3f, w4f);
}

// L3: z=0 cross d1; z=1 hmean d0 (co-resident)
__global__ __launch_bounds__(256, 2) void k_fused(
    const float* __restrict__ w2f, const float* __restrict__ w2b,
    const float* __restrict__ w3f, float* __restrict__ out)
{
    extern __shared__ float smf[];
    if (blockIdx.z == 0)
        cross_body(1, blockIdx.y, blockIdx.x * 64, smf, w2f, w2b, out);
    else
        hmean_body(0, blockIdx.y, blockIdx.x * 64, smf, w3f, out);
}

// L4: hmean d1 (32-i tiles, 128 thr)
__global__ __launch_bounds__(128) void k_hmean32(
    const int d, const float* __restrict__ w3f, float* __restrict__ out)
{
    extern __shared__ float hsm[];
    hmean32_body(d, blockIdx.y, blockIdx.x * 32, hsm, w3f, out);
}

// L5: m1 + m4 (256 thr, 8 columns/block — R12-measured config)
__global__ __launch_bounds__(256) void k_m14(
    const float* __restrict__ w1f, const float* __restrict__ w1b,
    const float* __restrict__ w4f, float* __restrict__ out)
{
    const int d = blockIdx.y;
    const int c = blockIdx.x * 8 + (threadIdx.x >> 5);
    const int lane = threadIdx.x & 31;
    const int b = c / Ss, i = c % Ss;
    const int jm = g_idx[d][c];

    const float* prow = g_pT[d] + c * HP;
    const float* ql = g_qT[d] + (b * Ss + Ss - 1) * HP;
    const float* qm = g_qT[d] + (b * Ss + jm) * HP;
    const float* wa1 = d ? w1b : w1f;

    float s1[2] = {0.f, 0.f}, s4[2] = {0.f, 0.f};
    for (int h = lane; h < Hh; h += 32) {
        float p = prow[h];
        float t1 = p * ql[h];
        float t4 = p * qm[h];
        #pragma unroll
        for (int l = 0; l < 2; ++l) {
            float a;
            a = wa1[l * Hh + h]; s1[l] += a * a * t1;
            a = w4f[l * Hh + h]; s4[l] += a * a * t4;
        }
    }
    #pragma unroll
    for (int l = 0; l < 2; ++l) { s1[l] = wred(s1[l]); s4[l] = wred(s4[l]); }
    if (lane == 0) {
        #pragma unroll
        for (int l = 0; l < 2; ++l) {
            out[(((0 + d) * Ss + i) * Bb + b) * Ll + l] =
                s1[l] * g_inv_w1p[d][l][c] * g_inv_w1ql[d][l][b];
            out[(((6 + d) * Ss + i) * Bb + b) * Ll + l] =
                s4[l] * g_inv_w4p[d][l][c] * g_inv_w4q[d][l][b * Ss + jm];
        }
    }
}

// ---------------- launch ----------------
extern "C" void kernel_launch(void* const* d_in, const int* in_sizes, int n_in,
                              void* d_out, int out_size) {
    const float* p_f = (const float*)d_in[0];
    const float* p_b = (const float*)d_in[1];
    const float* q_f = (const float*)d_in[2];
    const float* q_b = (const float*)d_in[3];
    const float* w1f = (const float*)d_in[4];
    const float* w1b = (const float*)d_in[5];
    const float* w2f = (const float*)d_in[6];
    const float* w2b = (const float*)d_in[7];
    const float* w3f = (const float*)d_in[8];
    // w3b (d_in[9]) intentionally unused: reference uses w3f/w4f for both directions
    const float* w4f = (const float*)d_in[10];
    float* out = (float*)d_out;

    cudaFuncSetAttribute(k_phase1, cudaFuncAttributeMaxDynamicSharedMemorySize,
                         CROSS_SMEM_BYTES);
    cudaFuncSetAttribute(k_fused, cudaFuncAttributeMaxDynamicSharedMemorySize,
                         CROSS_SMEM_BYTES);
    cudaFuncSetAttribute(k_hmean32, cudaFuncAttributeMaxDynamicSharedMemorySize,
                         HM32_SMEM_BYTES);

    k_transpose_d0<<<dim3(Ss / 64, Bb, 2), 256, TR_SMEM_BYTES>>>(
        p_f, p_b, q_f, q_b, w1f, w1b, w2f, w2b, w3f, w4f);
    k_phase1<<<dim3(Ss / 64, Bb, 3), 256, CROSS_SMEM_BYTES>>>(
        p_f, p_b, q_f, q_b, w1f, w1b, w2f, w2b, w3f, w4f, out);
    k_fused<<<dim3(Ss / 64, Bb, 2), 256, CROSS_SMEM_BYTES>>>(w2f, w2b, w3f, out);
    k_hmean32<<<dim3(Ss / 32, Bb), 128, HM32_SMEM_BYTES>>>(1, w3f, out);
    k_m14<<<dim3((Bb * Ss) / 8, 2), 256>>>(w1f, w1b, w4f, out);
}